// round 1
// baseline (speedup 1.0000x reference)
#include <cuda_runtime.h>
#include <cuda_bf16.h>

#define NN 100000
#define EE 800000
#define IN_C 128
#define HH 64
#define HEADS 2
#define BB 64
#define OUTC 10
#define EPSV 1e-5f

// ---------------- scratch (device globals; no allocation allowed) ----------------
__device__ float g_xw [NN*HH];
__device__ float g_x1 [NN*HH];
__device__ float g_agg[NN*HH];
__device__ float g_x2 [NN*HH];
__device__ float g_xg [NN*HEADS*HH];
__device__ float g_x3 [NN*HH];
__device__ float g_deg [NN];
__device__ float g_dinv[NN];
__device__ float g_cnt [NN];
__device__ float g_as[NN*HEADS];
__device__ float g_ad[NN*HEADS];
__device__ unsigned g_emax[NN*HEADS];
__device__ float g_mf  [NN*HEADS];
__device__ float g_esum[NN*HEADS];
__device__ float g_stats[2*HH];
__device__ float g_bnp  [2*HH];   // scale, shift
__device__ float g_pool[BB*HH];
__device__ float g_pcnt[BB];

// ---------------- helpers ----------------
__device__ __forceinline__ void redAdd4(float* addr, float4 v) {
    asm volatile("red.global.add.v4.f32 [%0], {%1,%2,%3,%4};"
                 :: "l"(addr), "f"(v.x), "f"(v.y), "f"(v.z), "f"(v.w) : "memory");
}
__device__ __forceinline__ unsigned fmap(float f) {
    unsigned u = __float_as_uint(f);
    return (u & 0x80000000u) ? ~u : (u | 0x80000000u);
}
__device__ __forceinline__ float funmap(unsigned u) {
    return (u & 0x80000000u) ? __uint_as_float(u ^ 0x80000000u) : __uint_as_float(~u);
}
__device__ __forceinline__ float lrelu(float v) { return v > 0.f ? v : 0.2f * v; }

// ---------------- degree / norm ----------------
__global__ void k_init_nodes() {
    int i = blockIdx.x * blockDim.x + threadIdx.x;
    if (i < NN) { g_deg[i] = 1.0f; g_cnt[i] = 0.0f; }
}
__global__ void k_edge_deg(const int* __restrict__ src, const int* __restrict__ dst) {
    int e = blockIdx.x * blockDim.x + threadIdx.x;
    if (e < EE) {
        int d = dst[e];
        atomicAdd(&g_deg[d], 1.0f);
        atomicAdd(&g_cnt[d], 1.0f);
        (void)src;
    }
}
__global__ void k_dinv() {
    int i = blockIdx.x * blockDim.x + threadIdx.x;
    if (i < NN) g_dinv[i] = rsqrtf(g_deg[i]);
}

// ---------------- GCN GEMM: xw = x @ W_gcn ; x1 = b + xw*dinv^2 (self-loop) ----------------
__global__ void k_gemm_gcn(const float* __restrict__ x, const float* __restrict__ Wg,
                           const float* __restrict__ bg) {
    __shared__ float Ws[IN_C*HH];   // 32KB
    __shared__ float Xs[32*IN_C];   // 16KB
    int tid = threadIdx.x;
    for (int i = tid; i < IN_C*HH; i += 256) Ws[i] = Wg[i];
    int row0 = blockIdx.x * 32;
    for (int i = tid; i < 32*IN_C; i += 256) {
        int r = i >> 7, k = i & 127;
        int gr = row0 + r;
        Xs[i] = (gr < NN) ? x[gr*IN_C + k] : 0.f;
    }
    __syncthreads();
    int c = tid & 63, rg = tid >> 6;
    #pragma unroll
    for (int j = 0; j < 8; j++) {
        int r = rg*8 + j;
        int gr = row0 + r;
        if (gr >= NN) continue;
        float acc = 0.f;
        #pragma unroll 8
        for (int k = 0; k < IN_C; k++) acc += Xs[r*IN_C + k] * Ws[k*HH + c];
        g_xw[gr*HH + c] = acc;
        float di = g_dinv[gr];
        g_x1[gr*HH + c] = bg[c] + acc * di * di;
    }
}

// ---------------- GCN scatter: x1[dst] += xw[src]*dinv[src]*dinv[dst] ----------------
__global__ void k_gcn_scatter(const int* __restrict__ src, const int* __restrict__ dst) {
    int t = blockIdx.x * blockDim.x + threadIdx.x;
    if (t >= EE*16) return;
    int e = t >> 4, q = t & 15;
    int s = src[e], d = dst[e];
    float w = g_dinv[s] * g_dinv[d];
    float4 v = *(const float4*)&g_xw[s*HH + q*4];
    v.x *= w; v.y *= w; v.z *= w; v.w *= w;
    redAdd4(&g_x1[d*HH + q*4], v);
}

// ---------------- BatchNorm (over N rows, 64ch) ----------------
__global__ void k_zero_stats() { if (threadIdx.x < 2*HH) g_stats[threadIdx.x] = 0.f; }

__global__ void k_bn_stats(int which) {
    const float* x = (which == 0) ? g_x1 : (which == 1) ? g_x2 : g_x3;
    __shared__ float ss[256], sq[256];
    int c = threadIdx.x & 63, slot = threadIdx.x >> 6;
    float s = 0.f, q = 0.f;
    for (int r = blockIdx.x*4 + slot; r < NN; r += gridDim.x*4) {
        float v = x[r*HH + c];
        s += v; q += v*v;
    }
    ss[threadIdx.x] = s; sq[threadIdx.x] = q;
    __syncthreads();
    if (slot == 0) {
        s = ss[c] + ss[c+64] + ss[c+128] + ss[c+192];
        q = sq[c] + sq[c+64] + sq[c+128] + sq[c+192];
        atomicAdd(&g_stats[c], s);
        atomicAdd(&g_stats[HH+c], q);
    }
}
__global__ void k_bn_finalize(const float* __restrict__ gamma, const float* __restrict__ beta) {
    int c = threadIdx.x;
    if (c < HH) {
        float invn = 1.0f / (float)NN;
        float mean = g_stats[c] * invn;
        float var  = g_stats[HH+c] * invn - mean*mean;
        float sc = gamma[c] * rsqrtf(var + EPSV);
        g_bnp[c] = sc;
        g_bnp[HH+c] = beta[c] - mean * sc;
    }
}
__global__ void k_bn_apply(int which) {   // relu(x*scale+shift); which==0 also zeroes agg
    int idx = blockIdx.x * blockDim.x + threadIdx.x;
    if (idx >= NN*16) return;
    float* x = (which == 0) ? g_x1 : (which == 1) ? g_x2 : g_x3;
    int base = idx * 4;
    int c = base & 63;
    float4 v = *(float4*)&x[base];
    v.x = fmaxf(v.x * g_bnp[c]   + g_bnp[HH+c],   0.f);
    v.y = fmaxf(v.y * g_bnp[c+1] + g_bnp[HH+c+1], 0.f);
    v.z = fmaxf(v.z * g_bnp[c+2] + g_bnp[HH+c+2], 0.f);
    v.w = fmaxf(v.w * g_bnp[c+3] + g_bnp[HH+c+3], 0.f);
    *(float4*)&x[base] = v;
    if (which == 0) *(float4*)&g_agg[base] = make_float4(0.f, 0.f, 0.f, 0.f);
}

// ---------------- SAGE ----------------
__global__ void k_sage_scatter(const int* __restrict__ src, const int* __restrict__ dst) {
    int t = blockIdx.x * blockDim.x + threadIdx.x;
    if (t >= EE*16) return;
    int e = t >> 4, q = t & 15;
    int s = src[e], d = dst[e];
    float4 v = *(const float4*)&g_x1[s*HH + q*4];
    redAdd4(&g_agg[d*HH + q*4], v);
}
__global__ void k_gemm_sage(const float* __restrict__ Wl, const float* __restrict__ Wr,
                            const float* __restrict__ bs) {
    __shared__ float WlS[HH*HH], WrS[HH*HH];  // 16KB + 16KB
    __shared__ float As[32*HH], Xs[32*HH];    // 8KB + 8KB
    int tid = threadIdx.x;
    for (int i = tid; i < HH*HH; i += 256) { WlS[i] = Wl[i]; WrS[i] = Wr[i]; }
    int row0 = blockIdx.x * 32;
    for (int i = tid; i < 32*HH; i += 256) {
        int r = i >> 6, k = i & 63;
        int gr = row0 + r;
        if (gr < NN) {
            float ic = 1.0f / fmaxf(g_cnt[gr], 1.0f);
            As[i] = g_agg[gr*HH + k] * ic;
            Xs[i] = g_x1[gr*HH + k];
        } else { As[i] = 0.f; Xs[i] = 0.f; }
    }
    __syncthreads();
    int c = tid & 63, rg = tid >> 6;
    #pragma unroll
    for (int j = 0; j < 8; j++) {
        int r = rg*8 + j;
        int gr = row0 + r;
        if (gr >= NN) continue;
        float acc = bs[c];
        #pragma unroll 8
        for (int k = 0; k < HH; k++)
            acc += As[r*HH + k] * WlS[k*HH + c] + Xs[r*HH + k] * WrS[k*HH + c];
        g_x2[gr*HH + c] = acc;
    }
}

// ---------------- GAT ----------------
__global__ void k_gemm_gat(const float* __restrict__ Wg) {
    __shared__ float Ws[HH*HEADS*HH];  // 64x128 = 32KB
    __shared__ float Xs[32*HH];        // 8KB
    int tid = threadIdx.x;
    for (int i = tid; i < HH*HEADS*HH; i += 256) Ws[i] = Wg[i];
    int row0 = blockIdx.x * 32;
    for (int i = tid; i < 32*HH; i += 256) {
        int r = i >> 6, k = i & 63;
        int gr = row0 + r;
        Xs[i] = (gr < NN) ? g_x2[gr*HH + k] : 0.f;
    }
    __syncthreads();
    int cc = tid & 127, rg = tid >> 7;
    #pragma unroll
    for (int j = 0; j < 16; j++) {
        int r = rg*16 + j;
        int gr = row0 + r;
        if (gr >= NN) continue;
        float acc = 0.f;
        #pragma unroll 8
        for (int k = 0; k < HH; k++) acc += Xs[r*HH + k] * Ws[k*128 + cc];
        g_xg[gr*128 + cc] = acc;
    }
}
__global__ void k_att(const float* __restrict__ att_s, const float* __restrict__ att_d) {
    int w = (blockIdx.x * blockDim.x + threadIdx.x) >> 5;
    if (w >= NN*HEADS) return;
    int lane = threadIdx.x & 31;
    int n = w >> 1, h = w & 1;
    const float* xr = &g_xg[n*128 + h*64];
    float v1 = xr[lane], v2 = xr[lane+32];
    float s = v1*att_s[h*64+lane] + v2*att_s[h*64+lane+32];
    float d = v1*att_d[h*64+lane] + v2*att_d[h*64+lane+32];
    #pragma unroll
    for (int o = 16; o; o >>= 1) {
        s += __shfl_xor_sync(0xffffffffu, s, o);
        d += __shfl_xor_sync(0xffffffffu, d, o);
    }
    if (lane == 0) {
        g_as[w] = s; g_ad[w] = d;
        g_emax[w] = fmap(lrelu(s + d));  // self-loop seeds the max
    }
}
__global__ void k_gat_max(const int* __restrict__ src, const int* __restrict__ dst) {
    int e = blockIdx.x * blockDim.x + threadIdx.x;
    if (e >= EE) return;
    int s = src[e], d = dst[e];
    #pragma unroll
    for (int h = 0; h < HEADS; h++) {
        float ev = lrelu(g_as[s*2+h] + g_ad[d*2+h]);
        atomicMax(&g_emax[d*2+h], fmap(ev));
    }
}
__global__ void k_gat_mid() {
    int w = blockIdx.x * blockDim.x + threadIdx.x;
    if (w >= NN*HEADS) return;
    float m = funmap(g_emax[w]);
    g_mf[w] = m;
    float es = lrelu(g_as[w] + g_ad[w]);
    g_esum[w] = __expf(es - m);  // self-loop contribution
}
__global__ void k_gat_sum(const int* __restrict__ src, const int* __restrict__ dst) {
    int e = blockIdx.x * blockDim.x + threadIdx.x;
    if (e >= EE) return;
    int s = src[e], d = dst[e];
    #pragma unroll
    for (int h = 0; h < HEADS; h++) {
        float ev = lrelu(g_as[s*2+h] + g_ad[d*2+h]);
        atomicAdd(&g_esum[d*2+h], __expf(ev - g_mf[d*2+h]));
    }
}
__global__ void k_gat_initx3(const float* __restrict__ bg) {
    int idx = blockIdx.x * blockDim.x + threadIdx.x;
    if (idx >= NN*HH) return;
    int n = idx >> 6, c = idx & 63;
    float a0 = __expf(lrelu(g_as[n*2]   + g_ad[n*2])   - g_mf[n*2])   / g_esum[n*2];
    float a1 = __expf(lrelu(g_as[n*2+1] + g_ad[n*2+1]) - g_mf[n*2+1]) / g_esum[n*2+1];
    g_x3[idx] = bg[c] + 0.5f * (g_xg[n*128 + c] * a0 + g_xg[n*128 + 64 + c] * a1);
}
__global__ void k_gat_scatter(const int* __restrict__ src, const int* __restrict__ dst) {
    int t = blockIdx.x * blockDim.x + threadIdx.x;
    if (t >= EE*16) return;
    int e = t >> 4, q = t & 15;
    int s = src[e], d = dst[e];
    float a0 = __expf(lrelu(g_as[s*2]   + g_ad[d*2])   - g_mf[d*2])   / g_esum[d*2];
    float a1 = __expf(lrelu(g_as[s*2+1] + g_ad[d*2+1]) - g_mf[d*2+1]) / g_esum[d*2+1];
    float4 v0 = *(const float4*)&g_xg[s*128 + q*4];
    float4 v1 = *(const float4*)&g_xg[s*128 + 64 + q*4];
    float4 v;
    v.x = 0.5f*(v0.x*a0 + v1.x*a1);
    v.y = 0.5f*(v0.y*a0 + v1.y*a1);
    v.z = 0.5f*(v0.z*a0 + v1.z*a1);
    v.w = 0.5f*(v0.w*a0 + v1.w*a1);
    redAdd4(&g_x3[d*HH + q*4], v);
}

// ---------------- pooling ----------------
__global__ void k_pool_init() {
    int i = blockIdx.x * blockDim.x + threadIdx.x;
    if (i < BB*HH) g_pool[i] = 0.f;
    if (i < BB) g_pcnt[i] = 0.f;
}
__global__ void k_pool(const int* __restrict__ batch) {
    int t = blockIdx.x * blockDim.x + threadIdx.x;
    if (t >= NN*16) return;
    int n = t >> 4, q = t & 15;
    int b = batch[n];
    float4 v = *(const float4*)&g_x3[n*HH + q*4];
    redAdd4(&g_pool[b*HH + q*4], v);
    if (q == 0) atomicAdd(&g_pcnt[b], 1.0f);
}

// ---------------- MLP head (single block) ----------------
__global__ void k_head(const float* __restrict__ Wm1, const float* __restrict__ bm1,
                       const float* __restrict__ gm,  const float* __restrict__ bem,
                       const float* __restrict__ Wm2, const float* __restrict__ bm2,
                       float* __restrict__ out) {
    __shared__ float smem[BB*128 + BB*HH];  // 48KB
    float* xc = smem;
    float* hb = smem + BB*128;
    int tid = threadIdx.x;
    for (int i = tid; i < BB*128; i += 256) {
        int b = i >> 7, k = i & 127;
        float v = (k < 64) ? g_pool[b*HH + k] / g_pcnt[b] : g_pool[b*HH + (k - 64)];
        xc[i] = v;
    }
    __syncthreads();
    for (int i = tid; i < BB*HH; i += 256) {
        int b = i >> 6, j = i & 63;
        float acc = bm1[j];
        const float* xr = &xc[b*128];
        #pragma unroll 8
        for (int k = 0; k < 128; k++) acc += xr[k] * Wm1[k*HH + j];
        hb[i] = acc;
    }
    __syncthreads();
    float* scl = xc;        // xc no longer needed
    float* shf = xc + 64;
    if (tid < 64) {
        float s = 0.f, q = 0.f;
        for (int b = 0; b < BB; b++) { float v = hb[b*HH + tid]; s += v; q += v*v; }
        float mean = s / (float)BB;
        float var  = q / (float)BB - mean*mean;
        float sc = gm[tid] * rsqrtf(var + EPSV);
        scl[tid] = sc;
        shf[tid] = bem[tid] - mean * sc;
    }
    __syncthreads();
    for (int i = tid; i < BB*HH; i += 256) {
        int j = i & 63;
        hb[i] = fmaxf(hb[i]*scl[j] + shf[j], 0.f);
    }
    __syncthreads();
    for (int i = tid; i < BB*OUTC; i += 256) {
        int b = i / OUTC, o = i % OUTC;
        float acc = bm2[o];
        const float* hr = &hb[b*HH];
        #pragma unroll 8
        for (int j = 0; j < HH; j++) acc += hr[j] * Wm2[j*OUTC + o];
        out[i] = acc;
    }
}

// ---------------- launch ----------------
extern "C" void kernel_launch(void* const* d_in, const int* in_sizes, int n_in,
                              void* d_out, int out_size) {
    const float* x      = (const float*)d_in[0];
    const int*   ei     = (const int*)  d_in[1];
    const int*   batch  = (const int*)  d_in[2];
    const float* W_gcn  = (const float*)d_in[3];
    const float* b_gcn  = (const float*)d_in[4];
    const float* W_sl   = (const float*)d_in[5];
    const float* W_sr   = (const float*)d_in[6];
    const float* b_sage = (const float*)d_in[7];
    const float* W_gat  = (const float*)d_in[8];
    const float* att_s  = (const float*)d_in[9];
    const float* att_d  = (const float*)d_in[10];
    const float* b_gat  = (const float*)d_in[11];
    const float* g1     = (const float*)d_in[12];
    const float* be1    = (const float*)d_in[13];
    const float* g2     = (const float*)d_in[14];
    const float* be2    = (const float*)d_in[15];
    const float* g3     = (const float*)d_in[16];
    const float* be3    = (const float*)d_in[17];
    const float* W_m1   = (const float*)d_in[18];
    const float* b_m1   = (const float*)d_in[19];
    const float* gm     = (const float*)d_in[20];
    const float* bem    = (const float*)d_in[21];
    const float* W_m2   = (const float*)d_in[22];
    const float* b_m2   = (const float*)d_in[23];
    float* out = (float*)d_out;

    const int* src = ei;
    const int* dst = ei + EE;

    // degrees
    k_init_nodes<<<(NN+255)/256, 256>>>();
    k_edge_deg<<<(EE+255)/256, 256>>>(src, dst);
    k_dinv<<<(NN+255)/256, 256>>>();

    // GCN
    k_gemm_gcn<<<(NN+31)/32, 256>>>(x, W_gcn, b_gcn);
    k_gcn_scatter<<<(EE*16+255)/256, 256>>>(src, dst);
    k_zero_stats<<<1, 128>>>();
    k_bn_stats<<<256, 256>>>(0);
    k_bn_finalize<<<1, 64>>>(g1, be1);
    k_bn_apply<<<(NN*16+255)/256, 256>>>(0);   // also zeroes g_agg

    // SAGE
    k_sage_scatter<<<(EE*16+255)/256, 256>>>(src, dst);
    k_gemm_sage<<<(NN+31)/32, 256>>>(W_sl, W_sr, b_sage);
    k_zero_stats<<<1, 128>>>();
    k_bn_stats<<<256, 256>>>(1);
    k_bn_finalize<<<1, 64>>>(g2, be2);
    k_bn_apply<<<(NN*16+255)/256, 256>>>(1);

    // GAT
    k_gemm_gat<<<(NN+31)/32, 256>>>(W_gat);
    k_att<<<(NN*HEADS*32+255)/256, 256>>>(att_s, att_d);
    k_gat_max<<<(EE+255)/256, 256>>>(src, dst);
    k_gat_mid<<<(NN*HEADS+255)/256, 256>>>();
    k_gat_sum<<<(EE+255)/256, 256>>>(src, dst);
    k_gat_initx3<<<(NN*HH+255)/256, 256>>>(b_gat);
    k_gat_scatter<<<(EE*16+255)/256, 256>>>(src, dst);
    k_zero_stats<<<1, 128>>>();
    k_bn_stats<<<256, 256>>>(2);
    k_bn_finalize<<<1, 64>>>(g3, be3);
    k_bn_apply<<<(NN*16+255)/256, 256>>>(2);

    // pooling + head
    k_pool_init<<<(BB*HH+255)/256, 256>>>();
    k_pool<<<(NN*16+255)/256, 256>>>(batch);
    k_head<<<1, 256>>>(W_m1, b_m1, gm, bem, W_m2, b_m2, out);

    (void)in_sizes; (void)n_in; (void)out_size;
}

// round 2
// speedup vs baseline: 1.4987x; 1.4987x over previous
#include <cuda_runtime.h>
#include <cuda_bf16.h>

#define NN 100000
#define EE 800000
#define IN_C 128
#define HH 64
#define HEADS 2
#define BB 64
#define OUTC 10
#define EPSV 1e-5f
#define NB 391          // (NN+255)/256

// ---------------- scratch ----------------
__device__ float g_xw [NN*HH];
__device__ float g_x1 [NN*HH];
__device__ float g_agg[NN*HH];
__device__ float g_x2 [NN*HH];
__device__ float g_xg [NN*HEADS*HH];
__device__ float g_x3 [NN*HH];
__device__ float g_dinv[NN];
__device__ float g_cntinv[NN];
__device__ float g_as[NN*HEADS];
__device__ float g_ad[NN*HEADS];
__device__ float g_stats[2*HH];
__device__ float g_bnp  [2*HH];
__device__ float g_pool[BB*HH];
__device__ float g_pcnt[BB];
__device__ int g_idg[NN];
__device__ int g_rowoff[NN+1];
__device__ int g_bsum[512];
__device__ int g_cursor[NN];
__device__ int g_csr[EE];

__device__ __forceinline__ float lrelu(float v) { return v > 0.f ? v : 0.2f * v; }

// ---------------- CSR build ----------------
__global__ void k_zero_idg() {
    int i = blockIdx.x * blockDim.x + threadIdx.x;
    if (i < NN) g_idg[i] = 0;
}
__global__ void k_deg(const int* __restrict__ dst) {
    int e = blockIdx.x * blockDim.x + threadIdx.x;
    if (e < EE) atomicAdd(&g_idg[dst[e]], 1);
}
__global__ void k_scan1() {
    __shared__ int sh[256];
    int i = blockIdx.x * 256 + threadIdx.x;
    sh[threadIdx.x] = (i < NN) ? g_idg[i] : 0;
    __syncthreads();
    for (int o = 128; o; o >>= 1) {
        if (threadIdx.x < o) sh[threadIdx.x] += sh[threadIdx.x + o];
        __syncthreads();
    }
    if (threadIdx.x == 0) g_bsum[blockIdx.x] = sh[0];
}
__global__ void k_scan2() {
    __shared__ int sh[512];
    int t = threadIdx.x;
    int v = (t < NB) ? g_bsum[t] : 0;
    sh[t] = v; __syncthreads();
    for (int o = 1; o < 512; o <<= 1) {
        int add = (t >= o) ? sh[t - o] : 0;
        __syncthreads();
        sh[t] += add;
        __syncthreads();
    }
    if (t < NB) g_bsum[t] = sh[t] - v;   // exclusive block offsets
}
__global__ void k_scan3() {
    __shared__ int sh[256];
    int i = blockIdx.x * 256 + threadIdx.x;
    int v = (i < NN) ? g_idg[i] : 0;
    sh[threadIdx.x] = v; __syncthreads();
    for (int o = 1; o < 256; o <<= 1) {
        int add = (threadIdx.x >= o) ? sh[threadIdx.x - o] : 0;
        __syncthreads();
        sh[threadIdx.x] += add;
        __syncthreads();
    }
    if (i < NN) {
        g_rowoff[i] = sh[threadIdx.x] - v + g_bsum[blockIdx.x];
        g_dinv[i] = rsqrtf((float)(v + 1));
        g_cntinv[i] = 1.0f / (float)(v > 1 ? v : 1);
        g_cursor[i] = 0;
    }
    if (i == NN - 1) g_rowoff[NN] = EE;
}
__global__ void k_fill(const int* __restrict__ src, const int* __restrict__ dst) {
    int e = blockIdx.x * blockDim.x + threadIdx.x;
    if (e < EE) {
        int d = dst[e];
        int pos = atomicAdd(&g_cursor[d], 1);
        g_csr[g_rowoff[d] + pos] = src[e];
    }
}

// ---------------- GEMM 1: xw = x @ W_gcn (100k x 128 -> 64) ----------------
// block: 32 rows x 64 cols, 256 threads, 2x4 micro-tile
__global__ void k_gemm_gcn(const float* __restrict__ x, const float* __restrict__ Wg) {
    __shared__ float Ws[IN_C * HH];   // [k][c] 32KB
    __shared__ float Xs[32 * IN_C];   // [r][k] 16KB
    int tid = threadIdx.x;
    int row0 = blockIdx.x * 32;
    for (int i = tid; i < IN_C * HH / 4; i += 256)
        ((float4*)Ws)[i] = ((const float4*)Wg)[i];
    for (int i = tid; i < 32 * IN_C / 4; i += 256) {
        int r = i >> 5;                 // 32 float4 per row
        int gr = row0 + r;
        ((float4*)Xs)[i] = (gr < NN) ? ((const float4*)x)[gr * 32 + (i & 31)]
                                     : make_float4(0.f, 0.f, 0.f, 0.f);
    }
    __syncthreads();
    int ty = tid >> 4, tx = tid & 15;   // ty: 16 row-groups(2), tx: 16 col-groups(4)
    float acc[2][4] = {};
    const float* Xr = &Xs[(ty * 2) * IN_C];
    #pragma unroll 8
    for (int k = 0; k < IN_C; k++) {
        float4 wv = *(const float4*)&Ws[k * HH + tx * 4];
        float x0 = Xr[k], x1 = Xr[IN_C + k];
        acc[0][0] += x0 * wv.x; acc[0][1] += x0 * wv.y; acc[0][2] += x0 * wv.z; acc[0][3] += x0 * wv.w;
        acc[1][0] += x1 * wv.x; acc[1][1] += x1 * wv.y; acc[1][2] += x1 * wv.z; acc[1][3] += x1 * wv.w;
    }
    #pragma unroll
    for (int i = 0; i < 2; i++) {
        int gr = row0 + ty * 2 + i;
        if (gr < NN)
            *(float4*)&g_xw[gr * HH + tx * 4] = make_float4(acc[i][0], acc[i][1], acc[i][2], acc[i][3]);
    }
}

// ---------------- GCN gather: x1 = b + dinv[d]*(dinv[d]*xw[d] + sum dinv[s]*xw[s]) ----------------
__global__ void k_gcn_gather(const float* __restrict__ bg) {
    int w = (blockIdx.x * blockDim.x + threadIdx.x) >> 5;   // node, grid exact
    int lane = threadIdx.x & 31;
    int rs = g_rowoff[w], re = g_rowoff[w + 1];
    float dn = g_dinv[w];
    float acc0 = dn * g_xw[w * HH + lane];
    float acc1 = dn * g_xw[w * HH + 32 + lane];
    for (int base = rs; base < re; base += 32) {
        int j = base + lane;
        int sv = 0; float wt = 0.f;
        if (j < re) { sv = g_csr[j]; wt = g_dinv[sv]; }
        int cnt = min(32, re - base);
        for (int t = 0; t < cnt; t++) {
            int s = __shfl_sync(0xffffffffu, sv, t);
            float ww = __shfl_sync(0xffffffffu, wt, t);
            acc0 += ww * g_xw[s * HH + lane];
            acc1 += ww * g_xw[s * HH + 32 + lane];
        }
    }
    g_x1[w * HH + lane]      = bg[lane]      + dn * acc0;
    g_x1[w * HH + 32 + lane] = bg[lane + 32] + dn * acc1;
}

// ---------------- BatchNorm ----------------
__global__ void k_zero_stats() { if (threadIdx.x < 2 * HH) g_stats[threadIdx.x] = 0.f; }

__global__ void k_bn_stats(int which) {
    const float* x = (which == 0) ? g_x1 : (which == 1) ? g_x2 : g_x3;
    __shared__ float ss[256], sq[256];
    int c = threadIdx.x & 63, slot = threadIdx.x >> 6;
    float s = 0.f, q = 0.f;
    for (int r = blockIdx.x * 4 + slot; r < NN; r += gridDim.x * 4) {
        float v = x[r * HH + c];
        s += v; q += v * v;
    }
    ss[threadIdx.x] = s; sq[threadIdx.x] = q;
    __syncthreads();
    if (slot == 0) {
        s = ss[c] + ss[c + 64] + ss[c + 128] + ss[c + 192];
        q = sq[c] + sq[c + 64] + sq[c + 128] + sq[c + 192];
        atomicAdd(&g_stats[c], s);
        atomicAdd(&g_stats[HH + c], q);
    }
}
__global__ void k_bn_finalize(const float* __restrict__ gamma, const float* __restrict__ beta) {
    int c = threadIdx.x;
    if (c < HH) {
        float invn = 1.0f / (float)NN;
        float mean = g_stats[c] * invn;
        float var  = g_stats[HH + c] * invn - mean * mean;
        float sc = gamma[c] * rsqrtf(var + EPSV);
        g_bnp[c] = sc;
        g_bnp[HH + c] = beta[c] - mean * sc;
    }
}
__global__ void k_bn_apply(int which) {
    int idx = blockIdx.x * blockDim.x + threadIdx.x;   // grid exact NN*16
    float* x = (which == 0) ? g_x1 : (which == 1) ? g_x2 : g_x3;
    int base = idx * 4;
    int c = base & 63;
    float4 v = *(float4*)&x[base];
    v.x = fmaxf(v.x * g_bnp[c]     + g_bnp[HH + c],     0.f);
    v.y = fmaxf(v.y * g_bnp[c + 1] + g_bnp[HH + c + 1], 0.f);
    v.z = fmaxf(v.z * g_bnp[c + 2] + g_bnp[HH + c + 2], 0.f);
    v.w = fmaxf(v.w * g_bnp[c + 3] + g_bnp[HH + c + 3], 0.f);
    *(float4*)&x[base] = v;
}

// ---------------- SAGE ----------------
__global__ void k_sage_gather() {
    int w = (blockIdx.x * blockDim.x + threadIdx.x) >> 5;
    int lane = threadIdx.x & 31;
    int rs = g_rowoff[w], re = g_rowoff[w + 1];
    float acc0 = 0.f, acc1 = 0.f;
    for (int base = rs; base < re; base += 32) {
        int j = base + lane;
        int sv = 0;
        if (j < re) sv = g_csr[j];
        int cnt = min(32, re - base);
        for (int t = 0; t < cnt; t++) {
            int s = __shfl_sync(0xffffffffu, sv, t);
            acc0 += g_x1[s * HH + lane];
            acc1 += g_x1[s * HH + 32 + lane];
        }
    }
    float ic = g_cntinv[w];
    g_agg[w * HH + lane]      = acc0 * ic;
    g_agg[w * HH + 32 + lane] = acc1 * ic;
}
// block: 32 rows x 64 cols, 2x4 micro-tile, dual-matrix
__global__ void k_gemm_sage(const float* __restrict__ Wl, const float* __restrict__ Wr,
                            const float* __restrict__ bs) {
    __shared__ float WlS[HH * HH], WrS[HH * HH];   // 16KB each
    __shared__ float As[32 * HH], Xs[32 * HH];     // 8KB each
    int tid = threadIdx.x;
    int row0 = blockIdx.x * 32;
    for (int i = tid; i < HH * HH / 4; i += 256) {
        ((float4*)WlS)[i] = ((const float4*)Wl)[i];
        ((float4*)WrS)[i] = ((const float4*)Wr)[i];
    }
    for (int i = tid; i < 32 * HH / 4; i += 256) {
        int r = i >> 4;   // 16 float4 per row
        int gr = row0 + r;
        if (gr < NN) {
            ((float4*)As)[i] = *(const float4*)&g_agg[gr * HH + (i & 15) * 4];
            ((float4*)Xs)[i] = *(const float4*)&g_x1[gr * HH + (i & 15) * 4];
        } else {
            ((float4*)As)[i] = make_float4(0.f, 0.f, 0.f, 0.f);
            ((float4*)Xs)[i] = make_float4(0.f, 0.f, 0.f, 0.f);
        }
    }
    __syncthreads();
    int ty = tid >> 4, tx = tid & 15;
    float acc[2][4] = {};
    const float* Ar = &As[(ty * 2) * HH];
    const float* Xr = &Xs[(ty * 2) * HH];
    #pragma unroll 8
    for (int k = 0; k < HH; k++) {
        float4 wl = *(const float4*)&WlS[k * HH + tx * 4];
        float4 wr = *(const float4*)&WrS[k * HH + tx * 4];
        float a0 = Ar[k], a1 = Ar[HH + k];
        float x0 = Xr[k], x1 = Xr[HH + k];
        acc[0][0] += a0 * wl.x + x0 * wr.x; acc[0][1] += a0 * wl.y + x0 * wr.y;
        acc[0][2] += a0 * wl.z + x0 * wr.z; acc[0][3] += a0 * wl.w + x0 * wr.w;
        acc[1][0] += a1 * wl.x + x1 * wr.x; acc[1][1] += a1 * wl.y + x1 * wr.y;
        acc[1][2] += a1 * wl.z + x1 * wr.z; acc[1][3] += a1 * wl.w + x1 * wr.w;
    }
    #pragma unroll
    for (int i = 0; i < 2; i++) {
        int gr = row0 + ty * 2 + i;
        if (gr < NN) {
            float4 o = make_float4(acc[i][0] + bs[tx*4], acc[i][1] + bs[tx*4+1],
                                   acc[i][2] + bs[tx*4+2], acc[i][3] + bs[tx*4+3]);
            *(float4*)&g_x2[gr * HH + tx * 4] = o;
        }
    }
}

// ---------------- GAT ----------------
// block: 32 rows x 128 cols, 2x8 micro-tile
__global__ void k_gemm_gat(const float* __restrict__ Wg) {
    __shared__ float Ws[HH * 128];   // 32KB
    __shared__ float Xs[32 * HH];    // 8KB
    int tid = threadIdx.x;
    int row0 = blockIdx.x * 32;
    for (int i = tid; i < HH * 128 / 4; i += 256)
        ((float4*)Ws)[i] = ((const float4*)Wg)[i];
    for (int i = tid; i < 32 * HH / 4; i += 256) {
        int r = i >> 4;
        int gr = row0 + r;
        ((float4*)Xs)[i] = (gr < NN) ? *(const float4*)&g_x2[gr * HH + (i & 15) * 4]
                                     : make_float4(0.f, 0.f, 0.f, 0.f);
    }
    __syncthreads();
    int ty = tid >> 4, tx = tid & 15;   // tx: col groups of 8
    float acc[2][8] = {};
    const float* Xr = &Xs[(ty * 2) * HH];
    #pragma unroll 4
    for (int k = 0; k < HH; k++) {
        float4 w0 = *(const float4*)&Ws[k * 128 + tx * 8];
        float4 w1 = *(const float4*)&Ws[k * 128 + tx * 8 + 4];
        float x0 = Xr[k], x1 = Xr[HH + k];
        acc[0][0] += x0 * w0.x; acc[0][1] += x0 * w0.y; acc[0][2] += x0 * w0.z; acc[0][3] += x0 * w0.w;
        acc[0][4] += x0 * w1.x; acc[0][5] += x0 * w1.y; acc[0][6] += x0 * w1.z; acc[0][7] += x0 * w1.w;
        acc[1][0] += x1 * w0.x; acc[1][1] += x1 * w0.y; acc[1][2] += x1 * w0.z; acc[1][3] += x1 * w0.w;
        acc[1][4] += x1 * w1.x; acc[1][5] += x1 * w1.y; acc[1][6] += x1 * w1.z; acc[1][7] += x1 * w1.w;
    }
    #pragma unroll
    for (int i = 0; i < 2; i++) {
        int gr = row0 + ty * 2 + i;
        if (gr < NN) {
            *(float4*)&g_xg[gr * 128 + tx * 8]     = make_float4(acc[i][0], acc[i][1], acc[i][2], acc[i][3]);
            *(float4*)&g_xg[gr * 128 + tx * 8 + 4] = make_float4(acc[i][4], acc[i][5], acc[i][6], acc[i][7]);
        }
    }
}
__global__ void k_att(const float* __restrict__ att_s, const float* __restrict__ att_d) {
    int w = (blockIdx.x * blockDim.x + threadIdx.x) >> 5;   // (node,head), grid exact
    int lane = threadIdx.x & 31;
    int n = w >> 1, h = w & 1;
    const float* xr = &g_xg[n * 128 + h * 64];
    float v1 = xr[lane], v2 = xr[lane + 32];
    float s = v1 * att_s[h * 64 + lane] + v2 * att_s[h * 64 + lane + 32];
    float d = v1 * att_d[h * 64 + lane] + v2 * att_d[h * 64 + lane + 32];
    #pragma unroll
    for (int o = 16; o; o >>= 1) {
        s += __shfl_xor_sync(0xffffffffu, s, o);
        d += __shfl_xor_sync(0xffffffffu, d, o);
    }
    if (lane == 0) { g_as[w] = s; g_ad[w] = d; }
}
// warp per node: softmax over in-edges (+self) and weighted feature sum
__global__ void k_gat_node(const float* __restrict__ bg) {
    int n = (blockIdx.x * blockDim.x + threadIdx.x) >> 5;
    int lane = threadIdx.x & 31;
    int rs = g_rowoff[n], re = g_rowoff[n + 1];
    float ad0 = g_ad[n * 2], ad1 = g_ad[n * 2 + 1];
    float as0n = g_as[n * 2], as1n = g_as[n * 2 + 1];
    float m0 = lrelu(as0n + ad0), m1 = lrelu(as1n + ad1);
    // pass A: max
    for (int base = rs; base < re; base += 32) {
        int j = base + lane;
        float e0 = -1e30f, e1 = -1e30f;
        if (j < re) {
            int sv = g_csr[j];
            float2 a = *(const float2*)&g_as[sv * 2];
            e0 = lrelu(a.x + ad0);
            e1 = lrelu(a.y + ad1);
        }
        #pragma unroll
        for (int o = 16; o; o >>= 1) {
            e0 = fmaxf(e0, __shfl_xor_sync(0xffffffffu, e0, o));
            e1 = fmaxf(e1, __shfl_xor_sync(0xffffffffu, e1, o));
        }
        m0 = fmaxf(m0, e0); m1 = fmaxf(m1, e1);
    }
    // self contributions
    float ps0 = __expf(lrelu(as0n + ad0) - m0);
    float ps1 = __expf(lrelu(as1n + ad1) - m1);
    float h00 = ps0 * g_xg[n * 128 + lane];
    float h01 = ps0 * g_xg[n * 128 + 32 + lane];
    float h10 = ps1 * g_xg[n * 128 + 64 + lane];
    float h11 = ps1 * g_xg[n * 128 + 96 + lane];
    float psum0 = 0.f, psum1 = 0.f;   // lane partials
    // pass B: unnormalized weighted sum
    for (int base = rs; base < re; base += 32) {
        int j = base + lane;
        int sv = 0; float p0 = 0.f, p1 = 0.f;
        if (j < re) {
            sv = g_csr[j];
            float2 a = *(const float2*)&g_as[sv * 2];
            p0 = __expf(lrelu(a.x + ad0) - m0);
            p1 = __expf(lrelu(a.y + ad1) - m1);
        }
        psum0 += p0; psum1 += p1;
        int cnt = min(32, re - base);
        for (int t = 0; t < cnt; t++) {
            int s = __shfl_sync(0xffffffffu, sv, t);
            float pp0 = __shfl_sync(0xffffffffu, p0, t);
            float pp1 = __shfl_sync(0xffffffffu, p1, t);
            h00 += pp0 * g_xg[s * 128 + lane];
            h01 += pp0 * g_xg[s * 128 + 32 + lane];
            h10 += pp1 * g_xg[s * 128 + 64 + lane];
            h11 += pp1 * g_xg[s * 128 + 96 + lane];
        }
    }
    #pragma unroll
    for (int o = 16; o; o >>= 1) {
        psum0 += __shfl_xor_sync(0xffffffffu, psum0, o);
        psum1 += __shfl_xor_sync(0xffffffffu, psum1, o);
    }
    float inv0 = 1.0f / (psum0 + ps0);
    float inv1 = 1.0f / (psum1 + ps1);
    g_x3[n * HH + lane]      = bg[lane]      + 0.5f * (h00 * inv0 + h10 * inv1);
    g_x3[n * HH + 32 + lane] = bg[lane + 32] + 0.5f * (h01 * inv0 + h11 * inv1);
}

// ---------------- pooling (batch is sorted) ----------------
__global__ void k_pool_zero() {
    int i = blockIdx.x * blockDim.x + threadIdx.x;
    if (i < BB * HH) g_pool[i] = 0.f;
    if (i < BB) g_pcnt[i] = 0.f;
}
#define NPB 500
__global__ void k_pool_seg(const int* __restrict__ batch) {
    int c = threadIdx.x;            // 64 threads: channel
    int n0 = blockIdx.x * NPB;
    int n1 = n0 + NPB;
    float acc = 0.f, cnt = 0.f;
    int cur = batch[n0];
    for (int n = n0; n < n1; n++) {
        int b = batch[n];
        if (b != cur) {
            atomicAdd(&g_pool[cur * HH + c], acc);
            if (c == 0) atomicAdd(&g_pcnt[cur], cnt);
            acc = 0.f; cnt = 0.f; cur = b;
        }
        acc += g_x3[n * HH + c];
        cnt += 1.f;
    }
    atomicAdd(&g_pool[cur * HH + c], acc);
    if (c == 0) atomicAdd(&g_pcnt[cur], cnt);
}

// ---------------- MLP head ----------------
__global__ void k_head(const float* __restrict__ Wm1, const float* __restrict__ bm1,
                       const float* __restrict__ gm,  const float* __restrict__ bem,
                       const float* __restrict__ Wm2, const float* __restrict__ bm2,
                       float* __restrict__ out) {
    __shared__ float smem[BB * 128 + BB * HH];  // 48KB
    float* xc = smem;
    float* hb = smem + BB * 128;
    int tid = threadIdx.x;
    for (int i = tid; i < BB * 128; i += 256) {
        int b = i >> 7, k = i & 127;
        xc[i] = (k < 64) ? g_pool[b * HH + k] / g_pcnt[b] : g_pool[b * HH + (k - 64)];
    }
    __syncthreads();
    for (int i = tid; i < BB * HH; i += 256) {
        int b = i >> 6, j = i & 63;
        float acc = bm1[j];
        const float* xr = &xc[b * 128];
        #pragma unroll 8
        for (int k = 0; k < 128; k++) acc += xr[k] * Wm1[k * HH + j];
        hb[i] = acc;
    }
    __syncthreads();
    float* scl = xc;
    float* shf = xc + 64;
    if (tid < 64) {
        float s = 0.f, q = 0.f;
        for (int b = 0; b < BB; b++) { float v = hb[b * HH + tid]; s += v; q += v * v; }
        float mean = s / (float)BB;
        float var  = q / (float)BB - mean * mean;
        float sc = gm[tid] * rsqrtf(var + EPSV);
        scl[tid] = sc;
        shf[tid] = bem[tid] - mean * sc;
    }
    __syncthreads();
    for (int i = tid; i < BB * HH; i += 256) {
        int j = i & 63;
        hb[i] = fmaxf(hb[i] * scl[j] + shf[j], 0.f);
    }
    __syncthreads();
    for (int i = tid; i < BB * OUTC; i += 256) {
        int b = i / OUTC, o = i % OUTC;
        float acc = bm2[o];
        const float* hr = &hb[b * HH];
        #pragma unroll 8
        for (int j = 0; j < HH; j++) acc += hr[j] * Wm2[j * OUTC + o];
        out[i] = acc;
    }
}

// ---------------- launch ----------------
extern "C" void kernel_launch(void* const* d_in, const int* in_sizes, int n_in,
                              void* d_out, int out_size) {
    const float* x      = (const float*)d_in[0];
    const int*   ei     = (const int*)  d_in[1];
    const int*   batch  = (const int*)  d_in[2];
    const float* W_gcn  = (const float*)d_in[3];
    const float* b_gcn  = (const float*)d_in[4];
    const float* W_sl   = (const float*)d_in[5];
    const float* W_sr   = (const float*)d_in[6];
    const float* b_sage = (const float*)d_in[7];
    const float* W_gat  = (const float*)d_in[8];
    const float* att_s  = (const float*)d_in[9];
    const float* att_d  = (const float*)d_in[10];
    const float* b_gat  = (const float*)d_in[11];
    const float* g1     = (const float*)d_in[12];
    const float* be1    = (const float*)d_in[13];
    const float* g2     = (const float*)d_in[14];
    const float* be2    = (const float*)d_in[15];
    const float* g3     = (const float*)d_in[16];
    const float* be3    = (const float*)d_in[17];
    const float* W_m1   = (const float*)d_in[18];
    const float* b_m1   = (const float*)d_in[19];
    const float* gm     = (const float*)d_in[20];
    const float* bem    = (const float*)d_in[21];
    const float* W_m2   = (const float*)d_in[22];
    const float* b_m2   = (const float*)d_in[23];
    float* out = (float*)d_out;

    const int* src = ei;
    const int* dst = ei + EE;

    // CSR build
    k_zero_idg<<<NB, 256>>>();
    k_deg<<<(EE + 255) / 256, 256>>>(dst);
    k_scan1<<<NB, 256>>>();
    k_scan2<<<1, 512>>>();
    k_scan3<<<NB, 256>>>();
    k_fill<<<(EE + 255) / 256, 256>>>(src, dst);

    // GCN
    k_gemm_gcn<<<(NN + 31) / 32, 256>>>(x, W_gcn);
    k_gcn_gather<<<NN / 8, 256>>>(b_gcn);
    k_zero_stats<<<1, 128>>>();
    k_bn_stats<<<256, 256>>>(0);
    k_bn_finalize<<<1, 64>>>(g1, be1);
    k_bn_apply<<<NN * 16 / 256, 256>>>(0);

    // SAGE
    k_sage_gather<<<NN / 8, 256>>>();
    k_gemm_sage<<<(NN + 31) / 32, 256>>>(W_sl, W_sr, b_sage);
    k_zero_stats<<<1, 128>>>();
    k_bn_stats<<<256, 256>>>(1);
    k_bn_finalize<<<1, 64>>>(g2, be2);
    k_bn_apply<<<NN * 16 / 256, 256>>>(1);

    // GAT
    k_gemm_gat<<<(NN + 31) / 32, 256>>>(W_gat);
    k_att<<<NN * HEADS / 8, 256>>>(att_s, att_d);
    k_gat_node<<<NN / 8, 256>>>(b_gat);
    k_zero_stats<<<1, 128>>>();
    k_bn_stats<<<256, 256>>>(2);
    k_bn_finalize<<<1, 64>>>(g3, be3);
    k_bn_apply<<<NN * 16 / 256, 256>>>(2);

    // pool + head
    k_pool_zero<<<(BB * HH + 255) / 256, 256>>>();
    k_pool_seg<<<NN / NPB, 64>>>(batch);
    k_head<<<1, 256>>>(W_m1, b_m1, gm, bem, W_m2, b_m2, out);

    (void)in_sizes; (void)n_in; (void)out_size;
}